// round 11
// baseline (speedup 1.0000x reference)
#include <cuda_runtime.h>
#include <cfloat>
#include <math.h>

// Problem constants
#define NN 16384
#define MM 32768
#define KK 8
#define CC 256
#define CHUNK 2048
#define NCHUNK 16              // MM / CHUNK

// Scratch (device globals; no allocations allowed)
__device__ int g_chist[64];            // cond cell histogram (4x4x4)
__device__ int g_ccur[64];             // cond scatter cursors
__device__ int g_nhist[512];           // node cell histogram (8x8x8)
__device__ int g_ncur[512];            // node scatter cursors
__device__ __align__(16) float g_scx[MM];   // cell-sorted negated transformed cond x
__device__ __align__(16) float g_scy[MM];
__device__ __align__(16) float g_scz[MM];
__device__ __align__(16) int   g_sidx[MM];  // original cond index per sorted slot
__device__ int g_nperm[NN];                 // cell-sorted original node ids
__device__ __align__(16) float4 g_blo4[NCHUNK];  // per-chunk AABB lo (true coords)
__device__ __align__(16) float4 g_bhi4[NCHUNK];  // per-chunk AABB hi
__device__ float g_favg[NN * CC];      // weighted-average features
__device__ float g_h1[NN * CC];        // MLP intermediate 1
__device__ float g_h2[NN * CC];        // MLP intermediate 2
__device__ float g_tf[CC];             // timestep feature vector

// ---------------------------------------------------------------------------
// Prep kernels: zero, histograms, scans, scatters, chunk bounds
// ---------------------------------------------------------------------------
__global__ void k_zero() {
    int tid = threadIdx.x;
    for (int i = tid; i < 64; i += 256) g_chist[i] = 0;
    for (int i = tid; i < 512; i += 256) g_nhist[i] = 0;
}

__global__ void k_chist(const int* __restrict__ cond_c) {
    int i = blockIdx.x * 256 + threadIdx.x;
    int4 cc = ((const int4*)cond_c)[i];
    int cell = ((cc.y >> 8) << 4) | ((cc.z >> 8) << 2) | (cc.w >> 8);
    atomicAdd(&g_chist[cell], 1);
}

__global__ void k_nhist(const int* __restrict__ node_c) {
    int i = blockIdx.x * 256 + threadIdx.x;
    int4 nc = ((const int4*)node_c)[i];
    int cell = ((nc.y >> 7) << 6) | ((nc.z >> 7) << 3) | (nc.w >> 7);
    atomicAdd(&g_nhist[cell], 1);
}

__global__ void k_scan64() {   // 1 block, 64 threads: exclusive scan via smem
    __shared__ int t[64];
    int i = threadIdx.x;
    t[i] = g_chist[i];
    __syncthreads();
    if (i == 0) {
        int acc = 0;
        for (int j = 0; j < 64; ++j) { int v = t[j]; t[j] = acc; acc += v; }
    }
    __syncthreads();
    g_ccur[i] = t[i];
}

__global__ void k_scan512() {  // 1 block, 512 threads: Hillis-Steele inclusive -> exclusive
    __shared__ int t[512];
    int i = threadIdx.x;
    int v0 = g_nhist[i];
    t[i] = v0;
    __syncthreads();
    #pragma unroll
    for (int off = 1; off < 512; off <<= 1) {
        int v = (i >= off) ? t[i - off] : 0;
        __syncthreads();
        t[i] += v;
        __syncthreads();
    }
    g_ncur[i] = t[i] - v0;   // exclusive
}

__global__ void k_cscatter(const int* __restrict__ cond_c) {
    int i = blockIdx.x * 256 + threadIdx.x;
    int4 cc = ((const int4*)cond_c)[i];
    int cell = ((cc.y >> 8) << 4) | ((cc.z >> 8) << 2) | (cc.w >> 8);
    int pos = atomicAdd(&g_ccur[cell], 1);
    // exact reference transform, negated (dx = add(nx, negcx))
    g_scx[pos] = -__fmul_rn(__fadd_rn((float)cc.y, 0.5f), 0.01f);
    g_scy[pos] = -__fmul_rn(__fadd_rn((float)cc.z, 0.5f), 0.01f);
    g_scz[pos] = -__fmul_rn(__fadd_rn((float)cc.w, 0.5f), 0.01f);
    g_sidx[pos] = i;
}

__global__ void k_nscatter(const int* __restrict__ node_c) {
    int i = blockIdx.x * 256 + threadIdx.x;
    int4 nc = ((const int4*)node_c)[i];
    int cell = ((nc.y >> 7) << 6) | ((nc.z >> 7) << 3) | (nc.w >> 7);
    int pos = atomicAdd(&g_ncur[cell], 1);
    g_nperm[pos] = i;
}

__global__ void k_bounds() {   // 16 blocks x 256 threads: per-chunk AABB of true coords
    const unsigned FULL = 0xffffffffu;
    int c = blockIdx.x, tid = threadIdx.x;
    float lx = FLT_MAX, ly = FLT_MAX, lz = FLT_MAX;
    float hx = -FLT_MAX, hy = -FLT_MAX, hz = -FLT_MAX;
    for (int i = tid; i < CHUNK; i += 256) {
        float x = -g_scx[c * CHUNK + i];
        float y = -g_scy[c * CHUNK + i];
        float z = -g_scz[c * CHUNK + i];
        lx = fminf(lx, x); hx = fmaxf(hx, x);
        ly = fminf(ly, y); hy = fmaxf(hy, y);
        lz = fminf(lz, z); hz = fmaxf(hz, z);
    }
    #pragma unroll
    for (int o = 16; o; o >>= 1) {
        lx = fminf(lx, __shfl_xor_sync(FULL, lx, o));
        ly = fminf(ly, __shfl_xor_sync(FULL, ly, o));
        lz = fminf(lz, __shfl_xor_sync(FULL, lz, o));
        hx = fmaxf(hx, __shfl_xor_sync(FULL, hx, o));
        hy = fmaxf(hy, __shfl_xor_sync(FULL, hy, o));
        hz = fmaxf(hz, __shfl_xor_sync(FULL, hz, o));
    }
    __shared__ float r[8][6];
    if ((tid & 31) == 0) {
        int w = tid >> 5;
        r[w][0] = lx; r[w][1] = ly; r[w][2] = lz;
        r[w][3] = hx; r[w][4] = hy; r[w][5] = hz;
    }
    __syncthreads();
    if (tid == 0) {
        for (int w = 1; w < 8; ++w) {
            lx = fminf(lx, r[w][0]); ly = fminf(ly, r[w][1]); lz = fminf(lz, r[w][2]);
            hx = fmaxf(hx, r[w][3]); hy = fmaxf(hy, r[w][4]); hz = fmaxf(hz, r[w][5]);
        }
        g_blo4[c] = make_float4(lx, ly, lz, 0.f);
        g_bhi4[c] = make_float4(hx, hy, hz, 0.f);
    }
}

// ---------------------------------------------------------------------------
// Kernel 1: timestep embedding -> 2-layer MLP -> g_tf[256]
// ---------------------------------------------------------------------------
__global__ void k_tfeats(const float* __restrict__ t,
                         const float* __restrict__ Wt1, const float* __restrict__ bt1,
                         const float* __restrict__ Wt2, const float* __restrict__ bt2) {
    __shared__ float emb[96];
    __shared__ float h1[96];
    int tid = threadIdx.x;
    float tv = t[0];
    if (tid < 48) {
        const double c64 = -9.210340371976184 / 47.0;
        float cf = (float)c64;
        float arg = __fmul_rn((float)tid, cf);
        float f = (float)exp((double)arg);
        float e = __fmul_rn(tv, f);
        emb[tid]      = (float)sin((double)e);
        emb[tid + 48] = (float)cos((double)e);
    }
    __syncthreads();
    if (tid < 96) {
        float acc = 0.0f;
        #pragma unroll 8
        for (int j = 0; j < 96; ++j) acc += emb[j] * Wt1[tid * 96 + j];
        acc += bt1[tid];
        h1[tid] = (acc >= 0.0f) ? acc : 0.1f * acc;
    }
    __syncthreads();
    if (tid < 256) {
        float acc = 0.0f;
        #pragma unroll 8
        for (int j = 0; j < 96; ++j) acc += h1[j] * Wt2[tid * 96 + j];
        acc += bt2[tid];
        g_tf[tid] = acc;
    }
}

// ---------------------------------------------------------------------------
// Packed f32x2 helpers (two independent IEEE-RN fp32 lanes -> bit-exact)
// ---------------------------------------------------------------------------
__device__ __forceinline__ unsigned long long pack2(float x) {
    unsigned long long r;
    asm("mov.b64 %0, {%1, %1};" : "=l"(r) : "f"(x));
    return r;
}

__device__ __forceinline__ void ffma2(unsigned long long& acc,
                                      unsigned long long a, unsigned long long b) {
    asm("fma.rn.f32x2 %0, %1, %2, %0;" : "+l"(acc) : "l"(a), "l"(b));
}

__device__ __forceinline__ void unpack2(unsigned long long v, float& lo, float& hi) {
    asm("mov.b64 {%0, %1}, %2;" : "=f"(lo), "=f"(hi) : "l"(v));
}

// d_lane = fma(dz,dz, fma(dy,dy, dx*dx)) with dx = nx + (-cx)  (XLA scheme)
__device__ __forceinline__ void dist2x2(unsigned long long nx, unsigned long long ny,
                                        unsigned long long nz,
                                        unsigned long long cx, unsigned long long cy,
                                        unsigned long long cz,
                                        float& d0, float& d1) {
    asm("{\n\t"
        ".reg .b64 dx, dy, dz, t;\n\t"
        "add.rn.f32x2 dx, %2, %5;\n\t"
        "add.rn.f32x2 dy, %3, %6;\n\t"
        "add.rn.f32x2 dz, %4, %7;\n\t"
        "mul.rn.f32x2 t, dx, dx;\n\t"
        "fma.rn.f32x2 t, dy, dy, t;\n\t"
        "fma.rn.f32x2 t, dz, dz, t;\n\t"
        "mov.b64 {%0, %1}, t;\n\t"
        "}"
        : "=f"(d0), "=f"(d1)
        : "l"(nx), "l"(ny), "l"(nz), "l"(cx), "l"(cy), "l"(cz));
}

// Lexicographic (d, idx) insert: order-independent, matches top_k tie rule
// (lowest index among equal distances). Strict lex comparison.
__device__ __forceinline__ void insertlex(float d, int idx, float* bd, int* bi) {
    if (d < bd[KK - 1] || (d == bd[KK - 1] && idx < bi[KK - 1])) {
        bd[KK - 1] = d;
        bi[KK - 1] = idx;
        #pragma unroll
        for (int q = KK - 1; q > 0; --q) {
            if (bd[q] < bd[q - 1] || (bd[q] == bd[q - 1] && bi[q] < bi[q - 1])) {
                float td = bd[q]; bd[q] = bd[q - 1]; bd[q - 1] = td;
                int   ti = bi[q]; bi[q] = bi[q - 1]; bi[q - 1] = ti;
            }
        }
    }
}

union F4U {
    float4 v;
    unsigned long long u[2];
};

// Box lower-bound squared distance (conservative slop applied by caller)
__device__ __forceinline__ float lbox(float4 lo, float4 hi, float x, float y, float z) {
    float dx = fmaxf(fmaxf(lo.x - x, x - hi.x), 0.f);
    float dy = fmaxf(fmaxf(lo.y - y, y - hi.y), 0.f);
    float dz = fmaxf(fmaxf(lo.z - z, z - hi.z), 0.f);
    return dx * dx + dy * dy + dz * dz;
}

// Per-node inner step: 4 candidates/lane, ballot-guarded lex windows
__device__ __forceinline__ void knn_node(unsigned long long nx, unsigned long long ny,
                                         unsigned long long nz,
                                         const F4U& X, const F4U& Y, const F4U& Z,
                                         const int* si_s, int sbase,
                                         float* bd, int* bi, float& thr) {
    const unsigned FULL = 0xffffffffu;
    float d0, d1, d2, d3;
    dist2x2(nx, ny, nz, X.u[0], Y.u[0], Z.u[0], d0, d1);
    dist2x2(nx, ny, nz, X.u[1], Y.u[1], Z.u[1], d2, d3);
    float mn = fminf(fminf(d0, d1), fminf(d2, d3));
    unsigned mask = __ballot_sync(FULL, mn <= thr);
    while (mask) {
        int b = __ffs(mask) - 1; mask &= mask - 1;
        float bm = __shfl_sync(FULL, mn, b);
        if (bm > thr) continue;          // uniform recheck (thr tightened)
        float e0 = __shfl_sync(FULL, d0, b);
        float e1 = __shfl_sync(FULL, d1, b);
        float e2 = __shfl_sync(FULL, d2, b);
        float e3 = __shfl_sync(FULL, d3, b);
        int4 iq = *(const int4*)&si_s[sbase + b * 4];   // broadcast smem load
        insertlex(e0, iq.x, bd, bi);
        insertlex(e1, iq.y, bd, bi);
        insertlex(e2, iq.z, bd, bi);
        insertlex(e3, iq.w, bd, bi);
        thr = bd[KK - 1];
    }
}

// ---------------------------------------------------------------------------
// Kernel 2: spatially-pruned exact KNN + weights + feature gather, fused.
// Block = 16 co-located nodes (via node cell sort), 8 warps x 2 nodes.
// Chunks visited nearest-first; chunk skipped per node when its AABB lower
// bound (with conservative fp slop) exceeds bd[7]. Lex (d, idx) insert makes
// the result independent of visit order and identical to reference top_k.
// ---------------------------------------------------------------------------
__global__ void __launch_bounds__(256) k_knn(const int* __restrict__ node_c,
                                             const float* __restrict__ cond_feats) {
    __shared__ __align__(16) float sx[CHUNK];
    __shared__ __align__(16) float sy[CHUNK];
    __shared__ __align__(16) float sz[CHUNK];
    __shared__ __align__(16) int   si[CHUNK];
    __shared__ int s_order[NCHUNK];
    __shared__ int s_need;

    const int tid  = threadIdx.x;
    const int warp = tid >> 5;
    const int lane = tid & 31;
    const unsigned FULL = 0xffffffffu;

    const int slot = blockIdx.x * 16 + warp * 2;
    const int nid0 = g_nperm[slot];
    const int nid1 = g_nperm[slot + 1];

    // exact node transforms (scalar + packed)
    float n0x, n0y, n0z, n1x, n1y, n1z;
    {
        int4 a = ((const int4*)node_c)[nid0];
        int4 b = ((const int4*)node_c)[nid1];
        n0x = __fmul_rn(__fadd_rn((float)a.y, 8.0f), 0.05f);
        n0y = __fmul_rn(__fadd_rn((float)a.z, 8.0f), 0.05f);
        n0z = __fmul_rn(__fadd_rn((float)a.w, 8.0f), 0.05f);
        n1x = __fmul_rn(__fadd_rn((float)b.y, 8.0f), 0.05f);
        n1y = __fmul_rn(__fadd_rn((float)b.z, 8.0f), 0.05f);
        n1z = __fmul_rn(__fadd_rn((float)b.w, 8.0f), 0.05f);
    }
    unsigned long long px0 = pack2(n0x), py0 = pack2(n0y), pz0 = pack2(n0z);
    unsigned long long px1 = pack2(n1x), py1 = pack2(n1y), pz1 = pack2(n1z);

    // chunk visit order: nearest-first w.r.t. block's first node (heuristic;
    // correctness comes from the per-node skip bound, not the order)
    if (tid == 0) {
        int nf = g_nperm[blockIdx.x * 16];
        int4 nc = ((const int4*)node_c)[nf];
        float ax = ((float)nc.y + 8.f) * 0.05f;
        float ay = ((float)nc.z + 8.f) * 0.05f;
        float az = ((float)nc.w + 8.f) * 0.05f;
        float key[NCHUNK];
        int   ord[NCHUNK];
        for (int c = 0; c < NCHUNK; ++c) {
            key[c] = lbox(g_blo4[c], g_bhi4[c], ax, ay, az);
            ord[c] = c;
        }
        for (int a = 1; a < NCHUNK; ++a) {        // insertion sort ascending
            float kv = key[a]; int ov = ord[a];
            int b = a - 1;
            while (b >= 0 && key[b] > kv) { key[b + 1] = key[b]; ord[b + 1] = ord[b]; --b; }
            key[b + 1] = kv; ord[b + 1] = ov;
        }
        for (int c = 0; c < NCHUNK; ++c) s_order[c] = ord[c];
    }

    float bd0[KK], bd1[KK];
    int   bi0[KK], bi1[KK];
    #pragma unroll
    for (int s = 0; s < KK; ++s) {
        bd0[s] = FLT_MAX; bi0[s] = 0x7fffffff;
        bd1[s] = FLT_MAX; bi1[s] = 0x7fffffff;
    }
    float thr0 = FLT_MAX, thr1 = FLT_MAX;

    __syncthreads();

    for (int oc = 0; oc < NCHUNK; ++oc) {
        const int c = s_order[oc];
        float4 lo = g_blo4[c], hi = g_bhi4[c];
        float lb0 = lbox(lo, hi, n0x, n0y, n0z);
        float lb1 = lbox(lo, hi, n1x, n1y, n1z);
        // conservative skip: only when lb (with slop) strictly exceeds bd[7]
        bool need0 = (__fmaf_rn(lb0, 0.999f, -1e-4f) <= thr0);
        bool need1 = (__fmaf_rn(lb1, 0.999f, -1e-4f) <= thr1);

        if (tid == 0) s_need = 0;
        __syncthreads();
        if ((need0 || need1) && lane == 0) s_need = 1;   // benign race
        __syncthreads();

        if (s_need) {   // block loads chunk c
            const float4* gx = (const float4*)(g_scx + c * CHUNK);
            const float4* gy = (const float4*)(g_scy + c * CHUNK);
            const float4* gz = (const float4*)(g_scz + c * CHUNK);
            const int4*   gi = (const int4*)(g_sidx + c * CHUNK);
            #pragma unroll
            for (int i = 0; i < CHUNK / 4; i += 256) {
                ((float4*)sx)[i + tid] = gx[i + tid];
                ((float4*)sy)[i + tid] = gy[i + tid];
                ((float4*)sz)[i + tid] = gz[i + tid];
                ((int4*)si)[i + tid]   = gi[i + tid];
            }
        }
        __syncthreads();

        if (need0 || need1) {
            #pragma unroll 1
            for (int step = 0; step < CHUNK / 128; ++step) {
                const int jb = step * 128 + lane * 4;
                F4U X, Y, Z;
                X.v = *(const float4*)&sx[jb];
                Y.v = *(const float4*)&sy[jb];
                Z.v = *(const float4*)&sz[jb];
                if (need0) knn_node(px0, py0, pz0, X, Y, Z, si, step * 128, bd0, bi0, thr0);
                if (need1) knn_node(px1, py1, pz1, X, Y, Z, si, step * 128, bd1, bi1, thr1);
            }
        }
    }

    // Fused epilogue: weights + weighted feature gather (state replicated in
    // all lanes; bd ascending lex = reference order for the fp weight sums).
    #pragma unroll
    for (int u = 0; u < 2; ++u) {
        const float* bd = (u == 0) ? bd0 : bd1;
        const int*   bi = (u == 0) ? bi0 : bi1;
        const int    nid = (u == 0) ? nid0 : nid1;

        float w[KK];
        float wsum = 0.0f;
        #pragma unroll
        for (int k = 0; k < KK; ++k) {
            float dist = fmaxf(sqrtf(bd[k]), 1e-6f);
            w[k] = 1.0f / dist;
            wsum += w[k];
        }
        #pragma unroll
        for (int k = 0; k < KK; ++k) w[k] = w[k] / wsum;

        const float* rp[KK];
        #pragma unroll
        for (int k = 0; k < KK; ++k) rp[k] = cond_feats + (size_t)bi[k] * CC;

        float* outp = g_favg + (size_t)nid * CC;
        #pragma unroll
        for (int j = 0; j < 8; ++j) {
            int cc = lane + j * 32;
            float acc = 0.0f;
            #pragma unroll
            for (int k = 0; k < KK; ++k) acc = fmaf(w[k], rp[k][cc], acc);
            outp[cc] = acc;
        }
    }
}

// ---------------------------------------------------------------------------
// Kernel 4: packed-f32x2 SGEMM  Y[16384,256] = X @ W^T (+bias, act, tf)
// (unchanged from round 10 — 60.5us, at the fp32 SIMT MAC ceiling)
// ---------------------------------------------------------------------------
#define SP 132   // smem pitch (floats)
template<int ACT, int ADDTF>
__global__ void __launch_bounds__(256, 2) k_gemm(const float* __restrict__ X,
                                                 const float* __restrict__ W,
                                                 const float* __restrict__ bias,
                                                 float* __restrict__ Y) {
    __shared__ float As[2][8][SP];
    __shared__ float Bs[2][8][SP];

    const int t   = threadIdx.x;
    const int tx  = t & 15;
    const int ty  = t >> 4;
    const int row0 = blockIdx.x * 128;
    const int col0 = blockIdx.y * 128;

    const int lrow = t >> 1;
    const int lk4  = (t & 1) * 4;
    const float* Ag = X + (size_t)(row0 + lrow) * CC + lk4;
    const float* Bg = W + (size_t)(col0 + lrow) * CC + lk4;

    float4 afrag = *(const float4*)Ag;
    float4 bfrag = *(const float4*)Bg;

    As[0][lk4 + 0][lrow] = afrag.x;
    As[0][lk4 + 1][lrow] = afrag.y;
    As[0][lk4 + 2][lrow] = afrag.z;
    As[0][lk4 + 3][lrow] = afrag.w;
    Bs[0][lk4 + 0][lrow] = bfrag.x;
    Bs[0][lk4 + 1][lrow] = bfrag.y;
    Bs[0][lk4 + 2][lrow] = bfrag.z;
    Bs[0][lk4 + 3][lrow] = bfrag.w;
    __syncthreads();

    unsigned long long acc2[4][8];
    #pragma unroll
    for (int i = 0; i < 4; ++i)
        #pragma unroll
        for (int j = 0; j < 8; ++j) acc2[i][j] = 0ull;

    #pragma unroll 1
    for (int kt = 0; kt < 32; ++kt) {
        int buf = kt & 1;
        if (kt < 31) {
            afrag = *(const float4*)(Ag + (kt + 1) * 8);
            bfrag = *(const float4*)(Bg + (kt + 1) * 8);
        }

        #pragma unroll
        for (int kk = 0; kk < 8; ++kk) {
            F4U a0, a1, b0, b1;
            a0.v = *(const float4*)&As[buf][kk][ty * 8];
            a1.v = *(const float4*)&As[buf][kk][ty * 8 + 4];
            b0.v = *(const float4*)&Bs[buf][kk][tx * 8];
            b1.v = *(const float4*)&Bs[buf][kk][tx * 8 + 4];

            unsigned long long ap[4] = {a0.u[0], a0.u[1], a1.u[0], a1.u[1]};
            unsigned long long bp[8];
            bp[0] = pack2(b0.v.x); bp[1] = pack2(b0.v.y);
            bp[2] = pack2(b0.v.z); bp[3] = pack2(b0.v.w);
            bp[4] = pack2(b1.v.x); bp[5] = pack2(b1.v.y);
            bp[6] = pack2(b1.v.z); bp[7] = pack2(b1.v.w);

            #pragma unroll
            for (int i = 0; i < 4; ++i)
                #pragma unroll
                for (int j = 0; j < 8; ++j)
                    ffma2(acc2[i][j], ap[i], bp[j]);
        }

        if (kt < 31) {
            int nb = buf ^ 1;
            As[nb][lk4 + 0][lrow] = afrag.x;
            As[nb][lk4 + 1][lrow] = afrag.y;
            As[nb][lk4 + 2][lrow] = afrag.z;
            As[nb][lk4 + 3][lrow] = afrag.w;
            Bs[nb][lk4 + 0][lrow] = bfrag.x;
            Bs[nb][lk4 + 1][lrow] = bfrag.y;
            Bs[nb][lk4 + 2][lrow] = bfrag.z;
            Bs[nb][lk4 + 3][lrow] = bfrag.w;
            __syncthreads();
        }
    }

    float bb[8], tf[8];
    #pragma unroll
    for (int j = 0; j < 8; ++j) {
        int c = col0 + tx * 8 + j;
        bb[j] = bias[c];
        if (ADDTF) tf[j] = g_tf[c];
    }

    #pragma unroll
    for (int i2 = 0; i2 < 4; ++i2) {
        float oL[8], oH[8];
        #pragma unroll
        for (int j = 0; j < 8; ++j) {
            float lo, hi;
            unpack2(acc2[i2][j], lo, hi);
            float vL = lo + bb[j];
            float vH = hi + bb[j];
            if (ACT) {
                vL = (vL >= 0.0f) ? vL : 0.1f * vL;
                vH = (vH >= 0.0f) ? vH : 0.1f * vH;
            }
            if (ADDTF) { vL += tf[j]; vH += tf[j]; }
            oL[j] = vL; oH[j] = vH;
        }
        int rL = row0 + ty * 8 + 2 * i2;
        float4* ypL = (float4*)(Y + (size_t)rL * CC + col0 + tx * 8);
        ypL[0] = make_float4(oL[0], oL[1], oL[2], oL[3]);
        ypL[1] = make_float4(oL[4], oL[5], oL[6], oL[7]);
        float4* ypH = (float4*)(Y + (size_t)(rL + 1) * CC + col0 + tx * 8);
        ypH[0] = make_float4(oH[0], oH[1], oH[2], oH[3]);
        ypH[1] = make_float4(oH[4], oH[5], oH[6], oH[7]);
    }
}

// ---------------------------------------------------------------------------
extern "C" void kernel_launch(void* const* d_in, const int* in_sizes, int n_in,
                              void* d_out, int out_size) {
    const int*   node_c     = (const int*)d_in[0];
    const int*   cond_c     = (const int*)d_in[1];
    const float* cond_feats = (const float*)d_in[2];
    const float* t          = (const float*)d_in[3];
    const float* W_proj     = (const float*)d_in[4];
    const float* b_proj     = (const float*)d_in[5];
    const float* W_l1       = (const float*)d_in[6];
    const float* b_l1       = (const float*)d_in[7];
    const float* W_l2       = (const float*)d_in[8];
    const float* b_l2       = (const float*)d_in[9];
    const float* W_t1       = (const float*)d_in[10];
    const float* b_t1       = (const float*)d_in[11];
    const float* W_t2       = (const float*)d_in[12];
    const float* b_t2       = (const float*)d_in[13];
    float* out = (float*)d_out;

    float* h1; cudaGetSymbolAddress((void**)&h1, g_h1);
    float* h2; cudaGetSymbolAddress((void**)&h2, g_h2);
    float* fa; cudaGetSymbolAddress((void**)&fa, g_favg);

    // spatial sort prep
    k_zero<<<1, 256>>>();
    k_chist<<<MM / 256, 256>>>(cond_c);
    k_nhist<<<NN / 256, 256>>>(node_c);
    k_scan64<<<1, 64>>>();
    k_scan512<<<1, 512>>>();
    k_cscatter<<<MM / 256, 256>>>(cond_c);
    k_nscatter<<<NN / 256, 256>>>(node_c);
    k_bounds<<<NCHUNK, 256>>>();

    k_tfeats<<<1, 256>>>(t, W_t1, b_t1, W_t2, b_t2);

    k_knn<<<NN / 16, 256>>>(node_c, cond_feats);   // 1024 blocks, 8 warps x 2 nodes

    dim3 gg(NN / 128, CC / 128);
    k_gemm<0, 0><<<gg, 256>>>(fa, W_proj, b_proj, h1);
    k_gemm<1, 0><<<gg, 256>>>(h1, W_l1, b_l1, h2);
    k_gemm<0, 1><<<gg, 256>>>(h2, W_l2, b_l2, out);

    (void)in_sizes; (void)n_in; (void)out_size;
}

// round 12
// speedup vs baseline: 1.0066x; 1.0066x over previous
#include <cuda_runtime.h>
#include <cfloat>
#include <math.h>

// Problem constants
#define NN 16384
#define MM 32768
#define KK 8
#define CC 256
#define SUBT 2048              // max candidates per smem sub-tile
#define NCHUNK 16              // spatial chunks = 4-cell (x,y) columns

// Scratch (device globals; no allocations allowed)
__device__ int g_chist[64];            // cond cell histogram (4x4x4, z fastest)
__device__ int g_ccur[64];             // cond scatter cursors
__device__ int g_cstart[65];           // durable exclusive scan (chunk bounds)
__device__ int g_nhist[512];           // node cell histogram (8x8x8)
__device__ int g_ncur[512];            // node scatter cursors
__device__ __align__(16) float g_scx[MM];   // cell-sorted negated transformed cond x
__device__ __align__(16) float g_scy[MM];
__device__ __align__(16) float g_scz[MM];
__device__ __align__(16) int   g_sidx[MM];  // original cond index per sorted slot
__device__ int g_nperm[NN];                 // cell-sorted original node ids
__device__ __align__(16) float4 g_blo4[NCHUNK];  // per-chunk AABB lo (true coords)
__device__ __align__(16) float4 g_bhi4[NCHUNK];  // per-chunk AABB hi
__device__ float g_favg[NN * CC];      // weighted-average features
__device__ float g_h1[NN * CC];        // MLP intermediate 1
__device__ float g_h2[NN * CC];        // MLP intermediate 2
__device__ float g_tf[CC];             // timestep feature vector

// ---------------------------------------------------------------------------
// Prep kernels
// ---------------------------------------------------------------------------
__global__ void k_zero() {
    int tid = threadIdx.x;
    for (int i = tid; i < 64; i += 256) g_chist[i] = 0;
    for (int i = tid; i < 512; i += 256) g_nhist[i] = 0;
}

__global__ void k_chist(const int* __restrict__ cond_c) {
    int i = blockIdx.x * 256 + threadIdx.x;
    int4 cc = ((const int4*)cond_c)[i];
    int cell = ((cc.y >> 8) << 4) | ((cc.z >> 8) << 2) | (cc.w >> 8);
    atomicAdd(&g_chist[cell], 1);
}

__global__ void k_nhist(const int* __restrict__ node_c) {
    int i = blockIdx.x * 256 + threadIdx.x;
    int4 nc = ((const int4*)node_c)[i];
    int cell = ((nc.y >> 7) << 6) | ((nc.z >> 7) << 3) | (nc.w >> 7);
    atomicAdd(&g_nhist[cell], 1);
}

__global__ void k_scan64() {   // 1 block, 64 threads; also writes durable g_cstart
    __shared__ int t[64];
    int i = threadIdx.x;
    t[i] = g_chist[i];
    __syncthreads();
    if (i == 0) {
        int acc = 0;
        for (int j = 0; j < 64; ++j) {
            int v = t[j]; t[j] = acc; g_cstart[j] = acc; acc += v;
        }
        g_cstart[64] = acc;   // == MM
    }
    __syncthreads();
    g_ccur[i] = t[i];
}

__global__ void k_scan512() {  // 1 block, 512 threads: Hillis-Steele -> exclusive
    __shared__ int t[512];
    int i = threadIdx.x;
    int v0 = g_nhist[i];
    t[i] = v0;
    __syncthreads();
    #pragma unroll
    for (int off = 1; off < 512; off <<= 1) {
        int v = (i >= off) ? t[i - off] : 0;
        __syncthreads();
        t[i] += v;
        __syncthreads();
    }
    g_ncur[i] = t[i] - v0;   // exclusive
}

__global__ void k_cscatter(const int* __restrict__ cond_c) {
    int i = blockIdx.x * 256 + threadIdx.x;
    int4 cc = ((const int4*)cond_c)[i];
    int cell = ((cc.y >> 8) << 4) | ((cc.z >> 8) << 2) | (cc.w >> 8);
    int pos = atomicAdd(&g_ccur[cell], 1);
    // exact reference transform, negated (dx = add(nx, negcx))
    g_scx[pos] = -__fmul_rn(__fadd_rn((float)cc.y, 0.5f), 0.01f);
    g_scy[pos] = -__fmul_rn(__fadd_rn((float)cc.z, 0.5f), 0.01f);
    g_scz[pos] = -__fmul_rn(__fadd_rn((float)cc.w, 0.5f), 0.01f);
    g_sidx[pos] = i;
}

__global__ void k_nscatter(const int* __restrict__ node_c) {
    int i = blockIdx.x * 256 + threadIdx.x;
    int4 nc = ((const int4*)node_c)[i];
    int cell = ((nc.y >> 7) << 6) | ((nc.z >> 7) << 3) | (nc.w >> 7);
    int pos = atomicAdd(&g_ncur[cell], 1);
    g_nperm[pos] = i;
}

__global__ void k_bounds() {   // NCHUNK blocks: AABB over cell-aligned chunk
    const unsigned FULL = 0xffffffffu;
    int c = blockIdx.x, tid = threadIdx.x;
    int s = g_cstart[4 * c], e = g_cstart[4 * c + 4];
    float lx = FLT_MAX, ly = FLT_MAX, lz = FLT_MAX;
    float hx = -FLT_MAX, hy = -FLT_MAX, hz = -FLT_MAX;
    for (int i = s + tid; i < e; i += 256) {
        float x = -g_scx[i];
        float y = -g_scy[i];
        float z = -g_scz[i];
        lx = fminf(lx, x); hx = fmaxf(hx, x);
        ly = fminf(ly, y); hy = fmaxf(hy, y);
        lz = fminf(lz, z); hz = fmaxf(hz, z);
    }
    #pragma unroll
    for (int o = 16; o; o >>= 1) {
        lx = fminf(lx, __shfl_xor_sync(FULL, lx, o));
        ly = fminf(ly, __shfl_xor_sync(FULL, ly, o));
        lz = fminf(lz, __shfl_xor_sync(FULL, lz, o));
        hx = fmaxf(hx, __shfl_xor_sync(FULL, hx, o));
        hy = fmaxf(hy, __shfl_xor_sync(FULL, hy, o));
        hz = fmaxf(hz, __shfl_xor_sync(FULL, hz, o));
    }
    __shared__ float r[8][6];
    if ((tid & 31) == 0) {
        int w = tid >> 5;
        r[w][0] = lx; r[w][1] = ly; r[w][2] = lz;
        r[w][3] = hx; r[w][4] = hy; r[w][5] = hz;
    }
    __syncthreads();
    if (tid == 0) {
        for (int w = 1; w < 8; ++w) {
            lx = fminf(lx, r[w][0]); ly = fminf(ly, r[w][1]); lz = fminf(lz, r[w][2]);
            hx = fmaxf(hx, r[w][3]); hy = fmaxf(hy, r[w][4]); hz = fmaxf(hz, r[w][5]);
        }
        g_blo4[c] = make_float4(lx, ly, lz, 0.f);
        g_bhi4[c] = make_float4(hx, hy, hz, 0.f);
    }
}

// ---------------------------------------------------------------------------
// Kernel 1: timestep embedding -> 2-layer MLP -> g_tf[256]
// ---------------------------------------------------------------------------
__global__ void k_tfeats(const float* __restrict__ t,
                         const float* __restrict__ Wt1, const float* __restrict__ bt1,
                         const float* __restrict__ Wt2, const float* __restrict__ bt2) {
    __shared__ float emb[96];
    __shared__ float h1[96];
    int tid = threadIdx.x;
    float tv = t[0];
    if (tid < 48) {
        const double c64 = -9.210340371976184 / 47.0;
        float cf = (float)c64;
        float arg = __fmul_rn((float)tid, cf);
        float f = (float)exp((double)arg);
        float e = __fmul_rn(tv, f);
        emb[tid]      = (float)sin((double)e);
        emb[tid + 48] = (float)cos((double)e);
    }
    __syncthreads();
    if (tid < 96) {
        float acc = 0.0f;
        #pragma unroll 8
        for (int j = 0; j < 96; ++j) acc += emb[j] * Wt1[tid * 96 + j];
        acc += bt1[tid];
        h1[tid] = (acc >= 0.0f) ? acc : 0.1f * acc;
    }
    __syncthreads();
    if (tid < 256) {
        float acc = 0.0f;
        #pragma unroll 8
        for (int j = 0; j < 96; ++j) acc += h1[j] * Wt2[tid * 96 + j];
        acc += bt2[tid];
        g_tf[tid] = acc;
    }
}

// ---------------------------------------------------------------------------
// Packed f32x2 helpers (two independent IEEE-RN fp32 lanes -> bit-exact)
// ---------------------------------------------------------------------------
__device__ __forceinline__ unsigned long long pack2(float x) {
    unsigned long long r;
    asm("mov.b64 %0, {%1, %1};" : "=l"(r) : "f"(x));
    return r;
}

__device__ __forceinline__ void ffma2(unsigned long long& acc,
                                      unsigned long long a, unsigned long long b) {
    asm("fma.rn.f32x2 %0, %1, %2, %0;" : "+l"(acc) : "l"(a), "l"(b));
}

__device__ __forceinline__ void unpack2(unsigned long long v, float& lo, float& hi) {
    asm("mov.b64 {%0, %1}, %2;" : "=f"(lo), "=f"(hi) : "l"(v));
}

// d_lane = fma(dz,dz, fma(dy,dy, dx*dx)) with dx = nx + (-cx)  (XLA scheme)
__device__ __forceinline__ void dist2x2(unsigned long long nx, unsigned long long ny,
                                        unsigned long long nz,
                                        unsigned long long cx, unsigned long long cy,
                                        unsigned long long cz,
                                        float& d0, float& d1) {
    asm("{\n\t"
        ".reg .b64 dx, dy, dz, t;\n\t"
        "add.rn.f32x2 dx, %2, %5;\n\t"
        "add.rn.f32x2 dy, %3, %6;\n\t"
        "add.rn.f32x2 dz, %4, %7;\n\t"
        "mul.rn.f32x2 t, dx, dx;\n\t"
        "fma.rn.f32x2 t, dy, dy, t;\n\t"
        "fma.rn.f32x2 t, dz, dz, t;\n\t"
        "mov.b64 {%0, %1}, t;\n\t"
        "}"
        : "=f"(d0), "=f"(d1)
        : "l"(nx), "l"(ny), "l"(nz), "l"(cx), "l"(cy), "l"(cz));
}

// Lexicographic (d, idx) insert: order-independent, matches top_k tie rule.
__device__ __forceinline__ void insertlex(float d, int idx, float* bd, int* bi) {
    if (d < bd[KK - 1] || (d == bd[KK - 1] && idx < bi[KK - 1])) {
        bd[KK - 1] = d;
        bi[KK - 1] = idx;
        #pragma unroll
        for (int q = KK - 1; q > 0; --q) {
            if (bd[q] < bd[q - 1] || (bd[q] == bd[q - 1] && bi[q] < bi[q - 1])) {
                float td = bd[q]; bd[q] = bd[q - 1]; bd[q - 1] = td;
                int   ti = bi[q]; bi[q] = bi[q - 1]; bi[q - 1] = ti;
            }
        }
    }
}

union F4U {
    float4 v;
    unsigned long long u[2];
};

// Box lower-bound squared distance
__device__ __forceinline__ float lbox(float4 lo, float4 hi, float x, float y, float z) {
    float dx = fmaxf(fmaxf(lo.x - x, x - hi.x), 0.f);
    float dy = fmaxf(fmaxf(lo.y - y, y - hi.y), 0.f);
    float dz = fmaxf(fmaxf(lo.z - z, z - hi.z), 0.f);
    return dx * dx + dy * dy + dz * dz;
}

// Per-node inner step: 4 candidates/lane, ballot-guarded lex windows
__device__ __forceinline__ void knn_node(unsigned long long nx, unsigned long long ny,
                                         unsigned long long nz,
                                         const F4U& X, const F4U& Y, const F4U& Z,
                                         const int* si_s, int sbase,
                                         float* bd, int* bi, float& thr) {
    const unsigned FULL = 0xffffffffu;
    float d0, d1, d2, d3;
    dist2x2(nx, ny, nz, X.u[0], Y.u[0], Z.u[0], d0, d1);
    dist2x2(nx, ny, nz, X.u[1], Y.u[1], Z.u[1], d2, d3);
    float mn = fminf(fminf(d0, d1), fminf(d2, d3));
    unsigned mask = __ballot_sync(FULL, mn <= thr);
    while (mask) {
        int b = __ffs(mask) - 1; mask &= mask - 1;
        float bm = __shfl_sync(FULL, mn, b);
        if (bm > thr) continue;          // uniform recheck (thr tightened)
        float e0 = __shfl_sync(FULL, d0, b);
        float e1 = __shfl_sync(FULL, d1, b);
        float e2 = __shfl_sync(FULL, d2, b);
        float e3 = __shfl_sync(FULL, d3, b);
        int4 iq = *(const int4*)&si_s[sbase + b * 4];   // broadcast smem load
        insertlex(e0, iq.x, bd, bi);
        insertlex(e1, iq.y, bd, bi);
        insertlex(e2, iq.z, bd, bi);
        insertlex(e3, iq.w, bd, bi);
        thr = bd[KK - 1];
    }
}

// ---------------------------------------------------------------------------
// Kernel 2: spatially-pruned exact KNN + weights + feature gather, fused.
// Chunks are CELL-ALIGNED (x,y) columns -> tight 2.56x2.56x10.24 AABBs.
// Variable-length chunks walked in <=2048 sub-tiles, tail padded with finite
// far sentinels. Lex (d, idx) insert => order-independent, exact top_k.
// ---------------------------------------------------------------------------
__global__ void __launch_bounds__(256) k_knn(const int* __restrict__ node_c,
                                             const float* __restrict__ cond_feats) {
    __shared__ __align__(16) float sx[SUBT];
    __shared__ __align__(16) float sy[SUBT];
    __shared__ __align__(16) float sz[SUBT];
    __shared__ __align__(16) int   si[SUBT];
    __shared__ int s_order[NCHUNK];
    __shared__ int s_cs[65];
    __shared__ int s_need;

    const int tid  = threadIdx.x;
    const int warp = tid >> 5;
    const int lane = tid & 31;
    const unsigned FULL = 0xffffffffu;

    if (tid < 65) s_cs[tid] = g_cstart[tid];

    const int slot = blockIdx.x * 16 + warp * 2;
    const int nid0 = g_nperm[slot];
    const int nid1 = g_nperm[slot + 1];

    float n0x, n0y, n0z, n1x, n1y, n1z;
    {
        int4 a = ((const int4*)node_c)[nid0];
        int4 b = ((const int4*)node_c)[nid1];
        n0x = __fmul_rn(__fadd_rn((float)a.y, 8.0f), 0.05f);
        n0y = __fmul_rn(__fadd_rn((float)a.z, 8.0f), 0.05f);
        n0z = __fmul_rn(__fadd_rn((float)a.w, 8.0f), 0.05f);
        n1x = __fmul_rn(__fadd_rn((float)b.y, 8.0f), 0.05f);
        n1y = __fmul_rn(__fadd_rn((float)b.z, 8.0f), 0.05f);
        n1z = __fmul_rn(__fadd_rn((float)b.w, 8.0f), 0.05f);
    }
    unsigned long long px0 = pack2(n0x), py0 = pack2(n0y), pz0 = pack2(n0z);
    unsigned long long px1 = pack2(n1x), py1 = pack2(n1y), pz1 = pack2(n1z);

    // chunk visit order: nearest-first w.r.t. block's first node (heuristic)
    if (tid == 0) {
        int nf = g_nperm[blockIdx.x * 16];
        int4 nc = ((const int4*)node_c)[nf];
        float ax = ((float)nc.y + 8.f) * 0.05f;
        float ay = ((float)nc.z + 8.f) * 0.05f;
        float az = ((float)nc.w + 8.f) * 0.05f;
        float key[NCHUNK];
        int   ord[NCHUNK];
        for (int c = 0; c < NCHUNK; ++c) {
            key[c] = lbox(g_blo4[c], g_bhi4[c], ax, ay, az);
            ord[c] = c;
        }
        for (int a = 1; a < NCHUNK; ++a) {
            float kv = key[a]; int ov = ord[a];
            int b = a - 1;
            while (b >= 0 && key[b] > kv) { key[b + 1] = key[b]; ord[b + 1] = ord[b]; --b; }
            key[b + 1] = kv; ord[b + 1] = ov;
        }
        for (int c = 0; c < NCHUNK; ++c) s_order[c] = ord[c];
    }

    float bd0[KK], bd1[KK];
    int   bi0[KK], bi1[KK];
    #pragma unroll
    for (int s = 0; s < KK; ++s) {
        bd0[s] = FLT_MAX; bi0[s] = 0x7fffffff;
        bd1[s] = FLT_MAX; bi1[s] = 0x7fffffff;
    }
    float thr0 = FLT_MAX, thr1 = FLT_MAX;

    __syncthreads();

    for (int oc = 0; oc < NCHUNK; ++oc) {
        const int c = s_order[oc];
        const int cs = s_cs[c * 4];
        const int ce = s_cs[c * 4 + 4];
        float4 lo = g_blo4[c], hi = g_bhi4[c];
        float lb0 = lbox(lo, hi, n0x, n0y, n0z);
        float lb1 = lbox(lo, hi, n1x, n1y, n1z);
        bool need0 = (__fmaf_rn(lb0, 0.999f, -1e-4f) <= thr0);
        bool need1 = (__fmaf_rn(lb1, 0.999f, -1e-4f) <= thr1);

        if (tid == 0) s_need = 0;
        __syncthreads();
        if ((need0 || need1) && lane == 0) s_need = 1;   // benign race
        __syncthreads();

        if (!s_need) continue;   // block-uniform skip: no load, no sync hazard

        for (int off = cs; off < ce; off += SUBT) {
            const int len  = min(SUBT, ce - off);
            const int lenp = (len + 127) & ~127;

            // cooperative load + sentinel pad
            for (int i = tid; i < lenp; i += 256) {
                if (i < len) {
                    sx[i] = g_scx[off + i];
                    sy[i] = g_scy[off + i];
                    sz[i] = g_scz[off + i];
                    si[i] = g_sidx[off + i];
                } else {
                    sx[i] = 1e18f; sy[i] = 1e18f; sz[i] = 1e18f;
                    si[i] = 0x7ffffffe;
                }
            }
            __syncthreads();

            if (need0 || need1) {
                const int nsteps = lenp >> 7;
                #pragma unroll 1
                for (int step = 0; step < nsteps; ++step) {
                    const int jb = step * 128 + lane * 4;
                    F4U X, Y, Z;
                    X.v = *(const float4*)&sx[jb];
                    Y.v = *(const float4*)&sy[jb];
                    Z.v = *(const float4*)&sz[jb];
                    if (need0) knn_node(px0, py0, pz0, X, Y, Z, si, step * 128, bd0, bi0, thr0);
                    if (need1) knn_node(px1, py1, pz1, X, Y, Z, si, step * 128, bd1, bi1, thr1);
                }
            }
            __syncthreads();
        }
    }

    // Fused epilogue: weights + weighted feature gather
    #pragma unroll
    for (int u = 0; u < 2; ++u) {
        const float* bd = (u == 0) ? bd0 : bd1;
        const int*   bi = (u == 0) ? bi0 : bi1;
        const int    nid = (u == 0) ? nid0 : nid1;

        float w[KK];
        float wsum = 0.0f;
        #pragma unroll
        for (int k = 0; k < KK; ++k) {
            float dist = fmaxf(sqrtf(bd[k]), 1e-6f);
            w[k] = 1.0f / dist;
            wsum += w[k];
        }
        #pragma unroll
        for (int k = 0; k < KK; ++k) w[k] = w[k] / wsum;

        const float* rp[KK];
        #pragma unroll
        for (int k = 0; k < KK; ++k) rp[k] = cond_feats + (size_t)bi[k] * CC;

        float* outp = g_favg + (size_t)nid * CC;
        #pragma unroll
        for (int j = 0; j < 8; ++j) {
            int cc = lane + j * 32;
            float acc = 0.0f;
            #pragma unroll
            for (int k = 0; k < KK; ++k) acc = fmaf(w[k], rp[k][cc], acc);
            outp[cc] = acc;
        }
    }
}

// ---------------------------------------------------------------------------
// Kernel 4: packed-f32x2 SGEMM  Y[16384,256] = X @ W^T (+bias, act, tf)
// (unchanged — 60.5us, at the fp32 SIMT MAC ceiling)
// ---------------------------------------------------------------------------
#define SP 132   // smem pitch (floats)
template<int ACT, int ADDTF>
__global__ void __launch_bounds__(256, 2) k_gemm(const float* __restrict__ X,
                                                 const float* __restrict__ W,
                                                 const float* __restrict__ bias,
                                                 float* __restrict__ Y) {
    __shared__ float As[2][8][SP];
    __shared__ float Bs[2][8][SP];

    const int t   = threadIdx.x;
    const int tx  = t & 15;
    const int ty  = t >> 4;
    const int row0 = blockIdx.x * 128;
    const int col0 = blockIdx.y * 128;

    const int lrow = t >> 1;
    const int lk4  = (t & 1) * 4;
    const float* Ag = X + (size_t)(row0 + lrow) * CC + lk4;
    const float* Bg = W + (size_t)(col0 + lrow) * CC + lk4;

    float4 afrag = *(const float4*)Ag;
    float4 bfrag = *(const float4*)Bg;

    As[0][lk4 + 0][lrow] = afrag.x;
    As[0][lk4 + 1][lrow] = afrag.y;
    As[0][lk4 + 2][lrow] = afrag.z;
    As[0][lk4 + 3][lrow] = afrag.w;
    Bs[0][lk4 + 0][lrow] = bfrag.x;
    Bs[0][lk4 + 1][lrow] = bfrag.y;
    Bs[0][lk4 + 2][lrow] = bfrag.z;
    Bs[0][lk4 + 3][lrow] = bfrag.w;
    __syncthreads();

    unsigned long long acc2[4][8];
    #pragma unroll
    for (int i = 0; i < 4; ++i)
        #pragma unroll
        for (int j = 0; j < 8; ++j) acc2[i][j] = 0ull;

    #pragma unroll 1
    for (int kt = 0; kt < 32; ++kt) {
        int buf = kt & 1;
        if (kt < 31) {
            afrag = *(const float4*)(Ag + (kt + 1) * 8);
            bfrag = *(const float4*)(Bg + (kt + 1) * 8);
        }

        #pragma unroll
        for (int kk = 0; kk < 8; ++kk) {
            F4U a0, a1, b0, b1;
            a0.v = *(const float4*)&As[buf][kk][ty * 8];
            a1.v = *(const float4*)&As[buf][kk][ty * 8 + 4];
            b0.v = *(const float4*)&Bs[buf][kk][tx * 8];
            b1.v = *(const float4*)&Bs[buf][kk][tx * 8 + 4];

            unsigned long long ap[4] = {a0.u[0], a0.u[1], a1.u[0], a1.u[1]};
            unsigned long long bp[8];
            bp[0] = pack2(b0.v.x); bp[1] = pack2(b0.v.y);
            bp[2] = pack2(b0.v.z); bp[3] = pack2(b0.v.w);
            bp[4] = pack2(b1.v.x); bp[5] = pack2(b1.v.y);
            bp[6] = pack2(b1.v.z); bp[7] = pack2(b1.v.w);

            #pragma unroll
            for (int i = 0; i < 4; ++i)
                #pragma unroll
                for (int j = 0; j < 8; ++j)
                    ffma2(acc2[i][j], ap[i], bp[j]);
        }

        if (kt < 31) {
            int nb = buf ^ 1;
            As[nb][lk4 + 0][lrow] = afrag.x;
            As[nb][lk4 + 1][lrow] = afrag.y;
            As[nb][lk4 + 2][lrow] = afrag.z;
            As[nb][lk4 + 3][lrow] = afrag.w;
            Bs[nb][lk4 + 0][lrow] = bfrag.x;
            Bs[nb][lk4 + 1][lrow] = bfrag.y;
            Bs[nb][lk4 + 2][lrow] = bfrag.z;
            Bs[nb][lk4 + 3][lrow] = bfrag.w;
            __syncthreads();
        }
    }

    float bb[8], tf[8];
    #pragma unroll
    for (int j = 0; j < 8; ++j) {
        int c = col0 + tx * 8 + j;
        bb[j] = bias[c];
        if (ADDTF) tf[j] = g_tf[c];
    }

    #pragma unroll
    for (int i2 = 0; i2 < 4; ++i2) {
        float oL[8], oH[8];
        #pragma unroll
        for (int j = 0; j < 8; ++j) {
            float lo, hi;
            unpack2(acc2[i2][j], lo, hi);
            float vL = lo + bb[j];
            float vH = hi + bb[j];
            if (ACT) {
                vL = (vL >= 0.0f) ? vL : 0.1f * vL;
                vH = (vH >= 0.0f) ? vH : 0.1f * vH;
            }
            if (ADDTF) { vL += tf[j]; vH += tf[j]; }
            oL[j] = vL; oH[j] = vH;
        }
        int rL = row0 + ty * 8 + 2 * i2;
        float4* ypL = (float4*)(Y + (size_t)rL * CC + col0 + tx * 8);
        ypL[0] = make_float4(oL[0], oL[1], oL[2], oL[3]);
        ypL[1] = make_float4(oL[4], oL[5], oL[6], oL[7]);
        float4* ypH = (float4*)(Y + (size_t)(rL + 1) * CC + col0 + tx * 8);
        ypH[0] = make_float4(oH[0], oH[1], oH[2], oH[3]);
        ypH[1] = make_float4(oH[4], oH[5], oH[6], oH[7]);
    }
}

// ---------------------------------------------------------------------------
extern "C" void kernel_launch(void* const* d_in, const int* in_sizes, int n_in,
                              void* d_out, int out_size) {
    const int*   node_c     = (const int*)d_in[0];
    const int*   cond_c     = (const int*)d_in[1];
    const float* cond_feats = (const float*)d_in[2];
    const float* t          = (const float*)d_in[3];
    const float* W_proj     = (const float*)d_in[4];
    const float* b_proj     = (const float*)d_in[5];
    const float* W_l1       = (const float*)d_in[6];
    const float* b_l1       = (const float*)d_in[7];
    const float* W_l2       = (const float*)d_in[8];
    const float* b_l2       = (const float*)d_in[9];
    const float* W_t1       = (const float*)d_in[10];
    const float* b_t1       = (const float*)d_in[11];
    const float* W_t2       = (const float*)d_in[12];
    const float* b_t2       = (const float*)d_in[13];
    float* out = (float*)d_out;

    float* h1; cudaGetSymbolAddress((void**)&h1, g_h1);
    float* h2; cudaGetSymbolAddress((void**)&h2, g_h2);
    float* fa; cudaGetSymbolAddress((void**)&fa, g_favg);

    // spatial sort prep
    k_zero<<<1, 256>>>();
    k_chist<<<MM / 256, 256>>>(cond_c);
    k_nhist<<<NN / 256, 256>>>(node_c);
    k_scan64<<<1, 64>>>();
    k_scan512<<<1, 512>>>();
    k_cscatter<<<MM / 256, 256>>>(cond_c);
    k_nscatter<<<NN / 256, 256>>>(node_c);
    k_bounds<<<NCHUNK, 256>>>();

    k_tfeats<<<1, 256>>>(t, W_t1, b_t1, W_t2, b_t2);

    k_knn<<<NN / 16, 256>>>(node_c, cond_feats);   // 1024 blocks, 8 warps x 2 nodes

    dim3 gg(NN / 128, CC / 128);
    k_gemm<0, 0><<<gg, 256>>>(fa, W_proj, b_proj, h1);
    k_gemm<1, 0><<<gg, 256>>>(h1, W_l1, b_l1, h2);
    k_gemm<0, 1><<<gg, 256>>>(h2, W_l2, b_l2, out);

    (void)in_sizes; (void)n_in; (void)out_size;
}

// round 13
// speedup vs baseline: 1.3815x; 1.3725x over previous
#include <cuda_runtime.h>
#include <cfloat>
#include <math.h>

// Problem constants
#define NN 16384
#define MM 32768
#define KK 8
#define CC 256
#define PS 2560                // padded slots per chunk (pop ~2048 +- 45, 11 sigma safe)
#define NCHUNK 16              // chunks = (x,y) cell columns of a 4x4x4 grid

// Scratch (device globals; no allocations allowed)
__device__ int g_chist[64];                 // cond cell histogram
__device__ int g_cstart[65];                // exclusive scan of cell counts
__device__ int g_ccur[64];                  // scatter cursors
__device__ __align__(16) float g_px[NCHUNK * PS];   // padded, chunked, negated cond x
__device__ __align__(16) float g_py[NCHUNK * PS];
__device__ __align__(16) float g_pz[NCHUNK * PS];
__device__ __align__(16) int   g_pidx[NCHUNK * PS]; // original cond index (sentinel 0x7ffffffe)
__device__ float g_favg[NN * CC];      // weighted-average features
__device__ float g_h1[NN * CC];        // MLP intermediate 1
__device__ float g_h2[NN * CC];        // MLP intermediate 2
__device__ float g_tf[CC];             // timestep feature vector

// ---------------------------------------------------------------------------
// Prep kernels (all tiny)
// ---------------------------------------------------------------------------
__global__ void k_zero() {
    if (threadIdx.x < 64) g_chist[threadIdx.x] = 0;
}

__global__ void k_hist(const int* __restrict__ cond_c) {
    __shared__ int h[64];
    int tid = threadIdx.x;
    if (tid < 64) h[tid] = 0;
    __syncthreads();
    int i = blockIdx.x * 256 + tid;
    int4 cc = ((const int4*)cond_c)[i];
    int cell = ((cc.y >> 8) << 4) | ((cc.z >> 8) << 2) | (cc.w >> 8);
    atomicAdd(&h[cell], 1);
    __syncthreads();
    if (tid < 64 && h[tid]) atomicAdd(&g_chist[tid], h[tid]);
}

__global__ void k_scan64() {   // 64 threads; serial scan by t0 (64 elements, trivial)
    if (threadIdx.x == 0) {
        int acc = 0;
        for (int j = 0; j < 64; ++j) {
            int v = g_chist[j];
            g_cstart[j] = acc;
            g_ccur[j] = acc;
            acc += v;
        }
        g_cstart[64] = acc;
    }
}

__global__ void k_fill() {     // sentinel-fill padded arrays (160 blocks x 256)
    int i = blockIdx.x * 256 + threadIdx.x;
    g_px[i] = 1e18f;
    g_py[i] = 1e18f;
    g_pz[i] = 1e18f;
    g_pidx[i] = 0x7ffffffe;
}

__global__ void k_scatter(const int* __restrict__ cond_c) {
    int i = blockIdx.x * 256 + threadIdx.x;
    int4 cc = ((const int4*)cond_c)[i];
    int cell = ((cc.y >> 8) << 4) | ((cc.z >> 8) << 2) | (cc.w >> 8);
    int pos = atomicAdd(&g_ccur[cell], 1);          // global rank within cell run
    int chunk = cell >> 2;
    int pidx = chunk * PS + (pos - g_cstart[(chunk << 2)]);
    // exact reference transform, negated (dx = add(nx, negcx))
    g_px[pidx] = -__fmul_rn(__fadd_rn((float)cc.y, 0.5f), 0.01f);
    g_py[pidx] = -__fmul_rn(__fadd_rn((float)cc.z, 0.5f), 0.01f);
    g_pz[pidx] = -__fmul_rn(__fadd_rn((float)cc.w, 0.5f), 0.01f);
    g_pidx[pidx] = i;
}

// ---------------------------------------------------------------------------
// Kernel 1: timestep embedding -> 2-layer MLP -> g_tf[256]
// ---------------------------------------------------------------------------
__global__ void k_tfeats(const float* __restrict__ t,
                         const float* __restrict__ Wt1, const float* __restrict__ bt1,
                         const float* __restrict__ Wt2, const float* __restrict__ bt2) {
    __shared__ float emb[96];
    __shared__ float h1[96];
    int tid = threadIdx.x;
    float tv = t[0];
    if (tid < 48) {
        const double c64 = -9.210340371976184 / 47.0;
        float cf = (float)c64;
        float arg = __fmul_rn((float)tid, cf);
        float f = (float)exp((double)arg);
        float e = __fmul_rn(tv, f);
        emb[tid]      = (float)sin((double)e);
        emb[tid + 48] = (float)cos((double)e);
    }
    __syncthreads();
    if (tid < 96) {
        float acc = 0.0f;
        #pragma unroll 8
        for (int j = 0; j < 96; ++j) acc += emb[j] * Wt1[tid * 96 + j];
        acc += bt1[tid];
        h1[tid] = (acc >= 0.0f) ? acc : 0.1f * acc;
    }
    __syncthreads();
    if (tid < 256) {
        float acc = 0.0f;
        #pragma unroll 8
        for (int j = 0; j < 96; ++j) acc += h1[j] * Wt2[tid * 96 + j];
        acc += bt2[tid];
        g_tf[tid] = acc;
    }
}

// ---------------------------------------------------------------------------
// Packed f32x2 helpers (two independent IEEE-RN fp32 lanes -> bit-exact)
// ---------------------------------------------------------------------------
__device__ __forceinline__ unsigned long long pack2(float x) {
    unsigned long long r;
    asm("mov.b64 %0, {%1, %1};" : "=l"(r) : "f"(x));
    return r;
}

__device__ __forceinline__ void ffma2(unsigned long long& acc,
                                      unsigned long long a, unsigned long long b) {
    asm("fma.rn.f32x2 %0, %1, %2, %0;" : "+l"(acc) : "l"(a), "l"(b));
}

__device__ __forceinline__ void unpack2(unsigned long long v, float& lo, float& hi) {
    asm("mov.b64 {%0, %1}, %2;" : "=f"(lo), "=f"(hi) : "l"(v));
}

// d_lane = fma(dz,dz, fma(dy,dy, dx*dx)) with dx = nx + (-cx)  (XLA scheme)
__device__ __forceinline__ void dist2x2(unsigned long long nx, unsigned long long ny,
                                        unsigned long long nz,
                                        unsigned long long cx, unsigned long long cy,
                                        unsigned long long cz,
                                        float& d0, float& d1) {
    asm("{\n\t"
        ".reg .b64 dx, dy, dz, t;\n\t"
        "add.rn.f32x2 dx, %2, %5;\n\t"
        "add.rn.f32x2 dy, %3, %6;\n\t"
        "add.rn.f32x2 dz, %4, %7;\n\t"
        "mul.rn.f32x2 t, dx, dx;\n\t"
        "fma.rn.f32x2 t, dy, dy, t;\n\t"
        "fma.rn.f32x2 t, dz, dz, t;\n\t"
        "mov.b64 {%0, %1}, t;\n\t"
        "}"
        : "=f"(d0), "=f"(d1)
        : "l"(nx), "l"(ny), "l"(nz), "l"(cx), "l"(cy), "l"(cz));
}

// Lexicographic (d, idx) insert: order-independent, equals top_k's selection
// and tie rule (ascending d, ties by lower original index).
__device__ __forceinline__ void insertlex(float d, int idx, float* bd, int* bi) {
    if (d < bd[KK - 1] || (d == bd[KK - 1] && idx < bi[KK - 1])) {
        bd[KK - 1] = d;
        bi[KK - 1] = idx;
        #pragma unroll
        for (int q = KK - 1; q > 0; --q) {
            if (bd[q] < bd[q - 1] || (bd[q] == bd[q - 1] && bi[q] < bi[q - 1])) {
                float td = bd[q]; bd[q] = bd[q - 1]; bd[q - 1] = td;
                int   ti = bi[q]; bi[q] = bi[q - 1]; bi[q - 1] = ti;
            }
        }
    }
}

union F4U {
    float4 v;
    unsigned long long u[2];
};

// Analytic chunk AABB lower-bound distance^2 (chunk = (x,y) cell column).
// Conservative by construction; caller adds relative+absolute slop.
__device__ __forceinline__ float chunk_lb(int c, float nx, float ny, float nz) {
    float xlo = (float)(c >> 2) * 2.56f + 0.005f;
    float ylo = (float)(c & 3)  * 2.56f + 0.005f;
    float dx = fmaxf(fmaxf(xlo - nx, nx - (xlo + 2.55f)), 0.f);
    float dy = fmaxf(fmaxf(ylo - ny, ny - (ylo + 2.55f)), 0.f);
    float dz = fmaxf(fmaxf(0.005f - nz, nz - 10.235f), 0.f);
    return dx * dx + dy * dy + dz * dz;
}

// Warp-cooperative scan of one padded chunk straight from L2.
__device__ __forceinline__ void process_chunk(
    int c, int lane,
    unsigned long long px, unsigned long long py, unsigned long long pz,
    float* bd, int* bi, float& thr)
{
    const unsigned FULL = 0xffffffffu;
    const float4* gx = (const float4*)(g_px + c * PS);
    const float4* gy = (const float4*)(g_py + c * PS);
    const float4* gz = (const float4*)(g_pz + c * PS);

    #pragma unroll 1
    for (int step = 0; step < PS / 128; ++step) {
        int jb = step * 32 + lane;
        F4U X, Y, Z;
        X.v = gx[jb];
        Y.v = gy[jb];
        Z.v = gz[jb];

        float d0, d1, d2, d3;
        dist2x2(px, py, pz, X.u[0], Y.u[0], Z.u[0], d0, d1);
        dist2x2(px, py, pz, X.u[1], Y.u[1], Z.u[1], d2, d3);
        float mn = fminf(fminf(d0, d1), fminf(d2, d3));
        unsigned mask = __ballot_sync(FULL, mn <= thr);
        while (mask) {
            int b = __ffs(mask) - 1; mask &= mask - 1;
            float bm = __shfl_sync(FULL, mn, b);
            if (bm > thr) continue;            // thr tightened since ballot
            float e0 = __shfl_sync(FULL, d0, b);
            float e1 = __shfl_sync(FULL, d1, b);
            float e2 = __shfl_sync(FULL, d2, b);
            float e3 = __shfl_sync(FULL, d3, b);
            int4 iq = *(const int4*)&g_pidx[c * PS + step * 128 + b * 4];
            insertlex(e0, iq.x, bd, bi);
            insertlex(e1, iq.y, bd, bi);
            insertlex(e2, iq.z, bd, bi);
            insertlex(e3, iq.w, bd, bi);
            thr = bd[KK - 1];
        }
    }
}

// ---------------------------------------------------------------------------
// Kernel 2: branch-and-bound exact KNN + weights + feature gather, fused.
// 1 node per warp, fully independent warps, zero smem / zero syncs.
// Warm-up on the analytically-nearest chunk, then prune the other 15 by
// AABB lower bound with conservative slop. Lex (d, idx) selection is
// order-independent and bit-identical to reference top_k.
// ---------------------------------------------------------------------------
__global__ void __launch_bounds__(256) k_knn(const int* __restrict__ node_c,
                                             const float* __restrict__ cond_feats) {
    const int warp = threadIdx.x >> 5;
    const int lane = threadIdx.x & 31;
    const int n = blockIdx.x * 8 + warp;

    int4 nc = ((const int4*)node_c)[n];
    float nx = __fmul_rn(__fadd_rn((float)nc.y, 8.0f), 0.05f);
    float ny = __fmul_rn(__fadd_rn((float)nc.z, 8.0f), 0.05f);
    float nz = __fmul_rn(__fadd_rn((float)nc.w, 8.0f), 0.05f);
    unsigned long long px = pack2(nx), py = pack2(ny), pz = pack2(nz);

    float bd[KK];
    int   bi[KK];
    #pragma unroll
    for (int s = 0; s < KK; ++s) { bd[s] = FLT_MAX; bi[s] = 0x7fffffff; }
    float thr = FLT_MAX;

    // warm-up: analytically nearest chunk
    int cbest = 0;
    {
        float best = FLT_MAX;
        #pragma unroll
        for (int c = 0; c < NCHUNK; ++c) {
            float lb = chunk_lb(c, nx, ny, nz);
            if (lb < best) { best = lb; cbest = c; }
        }
    }
    process_chunk(cbest, lane, px, py, pz, bd, bi, thr);

    // prune remaining chunks
    #pragma unroll 1
    for (int c = 0; c < NCHUNK; ++c) {
        if (c == cbest) continue;
        float lb = chunk_lb(c, nx, ny, nz);
        if (__fmaf_rn(lb, 0.999f, -0.01f) <= thr)
            process_chunk(c, lane, px, py, pz, bd, bi, thr);
    }

    // fused epilogue: weights + weighted feature gather (state replicated;
    // bd ascending lex = reference summation order)
    float w[KK];
    float wsum = 0.0f;
    #pragma unroll
    for (int k = 0; k < KK; ++k) {
        float dist = fmaxf(sqrtf(bd[k]), 1e-6f);
        w[k] = 1.0f / dist;
        wsum += w[k];
    }
    #pragma unroll
    for (int k = 0; k < KK; ++k) w[k] = w[k] / wsum;

    const float* rp[KK];
    #pragma unroll
    for (int k = 0; k < KK; ++k) rp[k] = cond_feats + (size_t)bi[k] * CC;

    float* outp = g_favg + (size_t)n * CC;
    #pragma unroll
    for (int j = 0; j < 8; ++j) {
        int c = lane + j * 32;
        float acc = 0.0f;
        #pragma unroll
        for (int k = 0; k < KK; ++k) acc = fmaf(w[k], rp[k][c], acc);
        outp[c] = acc;
    }
}

// ---------------------------------------------------------------------------
// Kernel 4: packed-f32x2 SGEMM  Y[16384,256] = X @ W^T (+bias, act, tf)
// (proven 60.5us variant, unchanged)
// ---------------------------------------------------------------------------
#define SP 132   // smem pitch (floats)
template<int ACT, int ADDTF>
__global__ void __launch_bounds__(256, 2) k_gemm(const float* __restrict__ X,
                                                 const float* __restrict__ W,
                                                 const float* __restrict__ bias,
                                                 float* __restrict__ Y) {
    __shared__ float As[2][8][SP];
    __shared__ float Bs[2][8][SP];

    const int t   = threadIdx.x;
    const int tx  = t & 15;
    const int ty  = t >> 4;
    const int row0 = blockIdx.x * 128;
    const int col0 = blockIdx.y * 128;

    const int lrow = t >> 1;
    const int lk4  = (t & 1) * 4;
    const float* Ag = X + (size_t)(row0 + lrow) * CC + lk4;
    const float* Bg = W + (size_t)(col0 + lrow) * CC + lk4;

    float4 afrag = *(const float4*)Ag;
    float4 bfrag = *(const float4*)Bg;

    As[0][lk4 + 0][lrow] = afrag.x;
    As[0][lk4 + 1][lrow] = afrag.y;
    As[0][lk4 + 2][lrow] = afrag.z;
    As[0][lk4 + 3][lrow] = afrag.w;
    Bs[0][lk4 + 0][lrow] = bfrag.x;
    Bs[0][lk4 + 1][lrow] = bfrag.y;
    Bs[0][lk4 + 2][lrow] = bfrag.z;
    Bs[0][lk4 + 3][lrow] = bfrag.w;
    __syncthreads();

    unsigned long long acc2[4][8];
    #pragma unroll
    for (int i = 0; i < 4; ++i)
        #pragma unroll
        for (int j = 0; j < 8; ++j) acc2[i][j] = 0ull;

    #pragma unroll 1
    for (int kt = 0; kt < 32; ++kt) {
        int buf = kt & 1;
        if (kt < 31) {
            afrag = *(const float4*)(Ag + (kt + 1) * 8);
            bfrag = *(const float4*)(Bg + (kt + 1) * 8);
        }

        #pragma unroll
        for (int kk = 0; kk < 8; ++kk) {
            F4U a0, a1, b0, b1;
            a0.v = *(const float4*)&As[buf][kk][ty * 8];
            a1.v = *(const float4*)&As[buf][kk][ty * 8 + 4];
            b0.v = *(const float4*)&Bs[buf][kk][tx * 8];
            b1.v = *(const float4*)&Bs[buf][kk][tx * 8 + 4];

            unsigned long long ap[4] = {a0.u[0], a0.u[1], a1.u[0], a1.u[1]};
            unsigned long long bp[8];
            bp[0] = pack2(b0.v.x); bp[1] = pack2(b0.v.y);
            bp[2] = pack2(b0.v.z); bp[3] = pack2(b0.v.w);
            bp[4] = pack2(b1.v.x); bp[5] = pack2(b1.v.y);
            bp[6] = pack2(b1.v.z); bp[7] = pack2(b1.v.w);

            #pragma unroll
            for (int i = 0; i < 4; ++i)
                #pragma unroll
                for (int j = 0; j < 8; ++j)
                    ffma2(acc2[i][j], ap[i], bp[j]);
        }

        if (kt < 31) {
            int nb = buf ^ 1;
            As[nb][lk4 + 0][lrow] = afrag.x;
            As[nb][lk4 + 1][lrow] = afrag.y;
            As[nb][lk4 + 2][lrow] = afrag.z;
            As[nb][lk4 + 3][lrow] = afrag.w;
            Bs[nb][lk4 + 0][lrow] = bfrag.x;
            Bs[nb][lk4 + 1][lrow] = bfrag.y;
            Bs[nb][lk4 + 2][lrow] = bfrag.z;
            Bs[nb][lk4 + 3][lrow] = bfrag.w;
            __syncthreads();
        }
    }

    float bb[8], tf[8];
    #pragma unroll
    for (int j = 0; j < 8; ++j) {
        int c = col0 + tx * 8 + j;
        bb[j] = bias[c];
        if (ADDTF) tf[j] = g_tf[c];
    }

    #pragma unroll
    for (int i2 = 0; i2 < 4; ++i2) {
        float oL[8], oH[8];
        #pragma unroll
        for (int j = 0; j < 8; ++j) {
            float lo, hi;
            unpack2(acc2[i2][j], lo, hi);
            float vL = lo + bb[j];
            float vH = hi + bb[j];
            if (ACT) {
                vL = (vL >= 0.0f) ? vL : 0.1f * vL;
                vH = (vH >= 0.0f) ? vH : 0.1f * vH;
            }
            if (ADDTF) { vL += tf[j]; vH += tf[j]; }
            oL[j] = vL; oH[j] = vH;
        }
        int rL = row0 + ty * 8 + 2 * i2;
        float4* ypL = (float4*)(Y + (size_t)rL * CC + col0 + tx * 8);
        ypL[0] = make_float4(oL[0], oL[1], oL[2], oL[3]);
        ypL[1] = make_float4(oL[4], oL[5], oL[6], oL[7]);
        float4* ypH = (float4*)(Y + (size_t)(rL + 1) * CC + col0 + tx * 8);
        ypH[0] = make_float4(oH[0], oH[1], oH[2], oH[3]);
        ypH[1] = make_float4(oH[4], oH[5], oH[6], oH[7]);
    }
}

// ---------------------------------------------------------------------------
extern "C" void kernel_launch(void* const* d_in, const int* in_sizes, int n_in,
                              void* d_out, int out_size) {
    const int*   node_c     = (const int*)d_in[0];
    const int*   cond_c     = (const int*)d_in[1];
    const float* cond_feats = (const float*)d_in[2];
    const float* t          = (const float*)d_in[3];
    const float* W_proj     = (const float*)d_in[4];
    const float* b_proj     = (const float*)d_in[5];
    const float* W_l1       = (const float*)d_in[6];
    const float* b_l1       = (const float*)d_in[7];
    const float* W_l2       = (const float*)d_in[8];
    const float* b_l2       = (const float*)d_in[9];
    const float* W_t1       = (const float*)d_in[10];
    const float* b_t1       = (const float*)d_in[11];
    const float* W_t2       = (const float*)d_in[12];
    const float* b_t2       = (const float*)d_in[13];
    float* out = (float*)d_out;

    float* h1; cudaGetSymbolAddress((void**)&h1, g_h1);
    float* h2; cudaGetSymbolAddress((void**)&h2, g_h2);
    float* fa; cudaGetSymbolAddress((void**)&fa, g_favg);

    // prep: cell histogram -> scan -> sentinel fill -> padded chunked scatter
    k_zero<<<1, 64>>>();
    k_hist<<<MM / 256, 256>>>(cond_c);
    k_scan64<<<1, 64>>>();
    k_fill<<<(NCHUNK * PS) / 256, 256>>>();
    k_scatter<<<MM / 256, 256>>>(cond_c);

    k_tfeats<<<1, 256>>>(t, W_t1, b_t1, W_t2, b_t2);

    k_knn<<<NN / 8, 256>>>(node_c, cond_feats);   // 2048 blocks, 1 node/warp

    dim3 gg(NN / 128, CC / 128);
    k_gemm<0, 0><<<gg, 256>>>(fa, W_proj, b_proj, h1);
    k_gemm<1, 0><<<gg, 256>>>(h1, W_l1, b_l1, h2);
    k_gemm<0, 1><<<gg, 256>>>(h2, W_l2, b_l2, out);

    (void)in_sizes; (void)n_in; (void)out_size;
}